// round 1
// baseline (speedup 1.0000x reference)
#include <cuda_runtime.h>
#include <cuda_bf16.h>

// Problem constants
#define BB 8
#define SS 64
#define CC 128
#define DD 256
#define BC 1024              // BB*CC
#define TT 65536             // BC*SS tokens
#define HH 8
#define HD 32
#define KVH 4
#define BSCD 16777216        // BB*SS*CC*DD

// Scratch (allocation-free rule: __device__ globals)
__device__ float g_wfold[2][256 * 512];
__device__ float g_bfold[2][512];
__device__ float g_qkv[2ull * TT * 512];   // per token: [0:256)=Q, [256:384)=K, [384:512)=V
__device__ float g_att[2ull * TT * 256];   // pre-Wo attention output

// ---------------------------------------------------------------------------
// Kernel 1: fold LN gain/bias into QKV weights.
// grid (512, 2), block 256.  t=0: spec input, t=1: spat input.
// ---------------------------------------------------------------------------
__global__ __launch_bounds__(256) void fold_kernel(
    const float* __restrict__ Wq_s2t, const float* __restrict__ bq_s2t,
    const float* __restrict__ Wk_s2t, const float* __restrict__ bk_s2t,
    const float* __restrict__ Wv_s2t, const float* __restrict__ bv_s2t,
    const float* __restrict__ Wq_t2s, const float* __restrict__ bq_t2s,
    const float* __restrict__ Wk_t2s, const float* __restrict__ bk_t2s,
    const float* __restrict__ Wv_t2s, const float* __restrict__ bv_t2s,
    const float* __restrict__ g_spec_q, const float* __restrict__ b_spec_q,
    const float* __restrict__ g_spec_kv, const float* __restrict__ b_spec_kv,
    const float* __restrict__ g_spat_q, const float* __restrict__ b_spat_q,
    const float* __restrict__ g_spat_kv, const float* __restrict__ b_spat_kv)
{
    int n = blockIdx.x;      // output column in [0,512)
    int t = blockIdx.y;      // which input tensor
    int k = threadIdx.x;     // input dim in [0,256)

    const float *W, *g, *bln, *bbase;
    int nc, stride;
    if (t == 0) {
        if (n < 256)      { W = Wq_s2t; nc = n;       stride = 256; g = g_spec_q;  bln = b_spec_q;  bbase = bq_s2t; }
        else if (n < 384) { W = Wk_t2s; nc = n - 256; stride = 128; g = g_spec_kv; bln = b_spec_kv; bbase = bk_t2s; }
        else              { W = Wv_t2s; nc = n - 384; stride = 128; g = g_spec_kv; bln = b_spec_kv; bbase = bv_t2s; }
    } else {
        if (n < 256)      { W = Wq_t2s; nc = n;       stride = 256; g = g_spat_q;  bln = b_spat_q;  bbase = bq_t2s; }
        else if (n < 384) { W = Wk_s2t; nc = n - 256; stride = 128; g = g_spat_kv; bln = b_spat_kv; bbase = bk_s2t; }
        else              { W = Wv_s2t; nc = n - 384; stride = 128; g = g_spat_kv; bln = b_spat_kv; bbase = bv_s2t; }
    }

    float w = W[k * stride + nc];
    g_wfold[t][k * 512 + n] = g[k] * w;

    __shared__ float red[256];
    red[k] = bln[k] * w;
    __syncthreads();
    for (int o = 128; o > 0; o >>= 1) {
        if (k < o) red[k] += red[k + o];
        __syncthreads();
    }
    if (k == 0) g_bfold[t][n] = red[0] + bbase[nc];
}

// ---------------------------------------------------------------------------
// Kernel 2: fused LayerNorm-core + QKV projection.
// grid (BC, 4, 2), block 256.  Each block: 64 tokens x 128 output cols.
// smem: core tile 64x257 + weight chunk 64x128 (dynamic, 98560 B).
// ---------------------------------------------------------------------------
#define SMEM_GEMM_BYTES ((64 * 257 + 64 * 128) * 4)

__global__ __launch_bounds__(256) void ln_qkv_kernel(
    const float* __restrict__ x_spec, const float* __restrict__ x_spat)
{
    int bc = blockIdx.x, nt = blockIdx.y, t = blockIdx.z;
    const float* x = (t == 0) ? x_spec : x_spat;

    extern __shared__ float sm[];
    float* core = sm;                 // [64][257]
    float* wsm  = sm + 64 * 257;      // [64][128]

    int tid = threadIdx.x;
    int b = bc >> 7, c = bc & 127;
    const float* xb = x + ((size_t)b * SS * CC + c) * DD;   // row s at +s*CC*DD

    // load x tile (64 tokens x 256)
    for (int i = tid; i < 64 * 256; i += 256) {
        int r = i >> 8, k = i & 255;
        core[r * 257 + k] = xb[(size_t)r * CC * DD + k];
    }
    __syncthreads();

    // LayerNorm core in place: 8 warps, 8 tokens each
    int w = tid >> 5, lane = tid & 31;
    for (int tk = w; tk < 64; tk += 8) {
        float s1 = 0.f, s2 = 0.f;
        for (int k = lane; k < 256; k += 32) {
            float v = core[tk * 257 + k];
            s1 += v; s2 += v * v;
        }
        for (int o = 16; o > 0; o >>= 1) {
            s1 += __shfl_xor_sync(0xffffffffu, s1, o);
            s2 += __shfl_xor_sync(0xffffffffu, s2, o);
        }
        float mu   = s1 * (1.f / 256.f);
        float var  = s2 * (1.f / 256.f) - mu * mu;
        float rinv = rsqrtf(var + 1e-5f);
        for (int k = lane; k < 256; k += 32)
            core[tk * 257 + k] = (core[tk * 257 + k] - mu) * rinv;
    }
    __syncthreads();

    // GEMM: 64x128 tile, K=256 in chunks of 64
    const float* Wf = g_wfold[t];
    int tx = tid & 15, ty = tid >> 4;
    float acc[4][8];
    #pragma unroll
    for (int i = 0; i < 4; i++)
        #pragma unroll
        for (int j = 0; j < 8; j++) acc[i][j] = 0.f;

    for (int kc = 0; kc < 256; kc += 64) {
        for (int i = tid; i < 64 * 128; i += 256) {
            int kk = i >> 7, ccol = i & 127;
            wsm[i] = Wf[(size_t)(kc + kk) * 512 + nt * 128 + ccol];
        }
        __syncthreads();
        #pragma unroll 4
        for (int kk = 0; kk < 64; kk++) {
            float a[4], bb[8];
            #pragma unroll
            for (int i = 0; i < 4; i++) a[i] = core[(ty * 4 + i) * 257 + kc + kk];
            #pragma unroll
            for (int j = 0; j < 8; j++) bb[j] = wsm[kk * 128 + tx * 8 + j];
            #pragma unroll
            for (int i = 0; i < 4; i++)
                #pragma unroll
                for (int j = 0; j < 8; j++) acc[i][j] += a[i] * bb[j];
        }
        __syncthreads();
    }

    float* out = g_qkv + (size_t)t * TT * 512;
    const float* bf = g_bfold[t];
    #pragma unroll
    for (int i = 0; i < 4; i++) {
        int row = ty * 4 + i;
        size_t ro = ((size_t)bc * 64 + row) * 512 + nt * 128;
        #pragma unroll
        for (int j = 0; j < 8; j++) {
            int col = tx * 8 + j;
            out[ro + col] = acc[i][j] + bf[nt * 128 + col];
        }
    }
}

// ---------------------------------------------------------------------------
// Kernel 3: attention per (bc, head, gqa). 64 threads, one query row each.
// GQA t: Q from g_qkv[t], K/V from g_qkv[1-t], kv head = h/2.
// ---------------------------------------------------------------------------
__global__ __launch_bounds__(64) void attn_kernel()
{
    int bc = blockIdx.x, h = blockIdx.y, t = blockIdx.z;
    int tid = threadIdx.x;

    const float* Qbase = g_qkv + (size_t)t * TT * 512 + (size_t)bc * 64 * 512 + h * 32;
    int kvh = h >> 1;
    const float* Kbase = g_qkv + (size_t)(1 - t) * TT * 512 + (size_t)bc * 64 * 512 + 256 + kvh * 32;
    const float* Vbase = Kbase + 128;

    __shared__ float Qs[64][33], Ks[64][33], Vs[64][33];
    for (int i = tid; i < 64 * 32; i += 64) {
        int r = i >> 5, d = i & 31;
        Qs[r][d] = Qbase[(size_t)r * 512 + d];
        Ks[r][d] = Kbase[(size_t)r * 512 + d];
        Vs[r][d] = Vbase[(size_t)r * 512 + d];
    }
    __syncthreads();

    const float scale = 0.17677669529663687f;  // 1/sqrt(32)

    float q[32];
    #pragma unroll
    for (int d = 0; d < 32; d++) q[d] = Qs[tid][d];

    float sc[64];
    float mx = -3.0e38f;
    for (int j = 0; j < 64; j++) {
        float s = 0.f;
        #pragma unroll
        for (int d = 0; d < 32; d++) s += q[d] * Ks[j][d];
        s *= scale;
        sc[j] = s;
        mx = fmaxf(mx, s);
    }
    float sum = 0.f;
    for (int j = 0; j < 64; j++) {
        float e = __expf(sc[j] - mx);
        sc[j] = e; sum += e;
    }
    float rs = 1.f / sum;

    float o[32];
    #pragma unroll
    for (int d = 0; d < 32; d++) o[d] = 0.f;
    for (int j = 0; j < 64; j++) {
        float p = sc[j] * rs;
        #pragma unroll
        for (int d = 0; d < 32; d++) o[d] += p * Vs[j][d];
    }

    float* O = g_att + (size_t)t * TT * 256 + ((size_t)bc * 64 + tid) * 256 + h * 32;
    float4* O4 = (float4*)O;
    #pragma unroll
    for (int d = 0; d < 8; d++)
        O4[d] = make_float4(o[4*d], o[4*d+1], o[4*d+2], o[4*d+3]);
}

// ---------------------------------------------------------------------------
// Kernel 4: output projection + bias + gate + residual + transpose-back.
// grid (BC, 2, 2), block 256. Same GEMM skeleton as kernel 2 (no LN).
// ---------------------------------------------------------------------------
__global__ __launch_bounds__(256) void out_kernel(
    const float* __restrict__ x_spec, const float* __restrict__ x_spat,
    const float* __restrict__ Wo_s2t, const float* __restrict__ bo_s2t,
    const float* __restrict__ Wo_t2s, const float* __restrict__ bo_t2s,
    const float* __restrict__ gate_spec, const float* __restrict__ gate_spat,
    float* __restrict__ d_out)
{
    int bc = blockIdx.x, nt = blockIdx.y, t = blockIdx.z;
    const float* A  = g_att + (size_t)t * TT * 256 + (size_t)bc * 64 * 256;
    const float* W  = t ? Wo_t2s : Wo_s2t;
    const float* bo = t ? bo_t2s : bo_s2t;
    const float* x  = t ? x_spat : x_spec;
    float gv = t ? gate_spat[0] : gate_spec[0];
    float gate = 1.f / (1.f + __expf(-gv));

    extern __shared__ float sm[];
    float* as  = sm;              // [64][257]
    float* wsm = sm + 64 * 257;   // [64][128]

    int tid = threadIdx.x;
    for (int i = tid; i < 64 * 256; i += 256) {
        int r = i >> 8, k = i & 255;
        as[r * 257 + k] = A[(size_t)r * 256 + k];
    }
    __syncthreads();

    int tx = tid & 15, ty = tid >> 4;
    float acc[4][8];
    #pragma unroll
    for (int i = 0; i < 4; i++)
        #pragma unroll
        for (int j = 0; j < 8; j++) acc[i][j] = 0.f;

    for (int kc = 0; kc < 256; kc += 64) {
        for (int i = tid; i < 64 * 128; i += 256) {
            int kk = i >> 7, ccol = i & 127;
            wsm[i] = W[(size_t)(kc + kk) * 256 + nt * 128 + ccol];
        }
        __syncthreads();
        #pragma unroll 4
        for (int kk = 0; kk < 64; kk++) {
            float a[4], bb[8];
            #pragma unroll
            for (int i = 0; i < 4; i++) a[i] = as[(ty * 4 + i) * 257 + kc + kk];
            #pragma unroll
            for (int j = 0; j < 8; j++) bb[j] = wsm[kk * 128 + tx * 8 + j];
            #pragma unroll
            for (int i = 0; i < 4; i++)
                #pragma unroll
                for (int j = 0; j < 8; j++) acc[i][j] += a[i] * bb[j];
        }
        __syncthreads();
    }

    int b = bc >> 7, c = bc & 127;
    #pragma unroll
    for (int i = 0; i < 4; i++) {
        int s = ty * 4 + i;
        size_t gbase = (((size_t)b * SS + s) * CC + c) * DD + nt * 128;
        #pragma unroll
        for (int j = 0; j < 8; j++) {
            int col = tx * 8 + j;
            float val = acc[i][j] + bo[nt * 128 + col];
            d_out[(size_t)t * BSCD + gbase + col] = x[gbase + col] + gate * val;
        }
    }
}

// ---------------------------------------------------------------------------
// Host launcher
// ---------------------------------------------------------------------------
extern "C" void kernel_launch(void* const* d_in, const int* in_sizes, int n_in,
                              void* d_out, int out_size)
{
    const float* x_spec      = (const float*)d_in[0];
    const float* x_spat      = (const float*)d_in[1];
    const float* ln_spec_q_g = (const float*)d_in[2];
    const float* ln_spec_q_b = (const float*)d_in[3];
    const float* ln_spec_kv_g= (const float*)d_in[4];
    const float* ln_spec_kv_b= (const float*)d_in[5];
    const float* ln_spat_q_g = (const float*)d_in[6];
    const float* ln_spat_q_b = (const float*)d_in[7];
    const float* ln_spat_kv_g= (const float*)d_in[8];
    const float* ln_spat_kv_b= (const float*)d_in[9];
    const float* Wq_s2t = (const float*)d_in[10];
    const float* bq_s2t = (const float*)d_in[11];
    const float* Wk_s2t = (const float*)d_in[12];
    const float* bk_s2t = (const float*)d_in[13];
    const float* Wv_s2t = (const float*)d_in[14];
    const float* bv_s2t = (const float*)d_in[15];
    const float* Wo_s2t = (const float*)d_in[16];
    const float* bo_s2t = (const float*)d_in[17];
    const float* Wq_t2s = (const float*)d_in[18];
    const float* bq_t2s = (const float*)d_in[19];
    const float* Wk_t2s = (const float*)d_in[20];
    const float* bk_t2s = (const float*)d_in[21];
    const float* Wv_t2s = (const float*)d_in[22];
    const float* bv_t2s = (const float*)d_in[23];
    const float* Wo_t2s = (const float*)d_in[24];
    const float* bo_t2s = (const float*)d_in[25];
    const float* gate_spec = (const float*)d_in[26];
    const float* gate_spat = (const float*)d_in[27];
    float* out = (float*)d_out;

    cudaFuncSetAttribute(ln_qkv_kernel, cudaFuncAttributeMaxDynamicSharedMemorySize, SMEM_GEMM_BYTES);
    cudaFuncSetAttribute(out_kernel,    cudaFuncAttributeMaxDynamicSharedMemorySize, SMEM_GEMM_BYTES);

    fold_kernel<<<dim3(512, 2), 256>>>(
        Wq_s2t, bq_s2t, Wk_s2t, bk_s2t, Wv_s2t, bv_s2t,
        Wq_t2s, bq_t2s, Wk_t2s, bk_t2s, Wv_t2s, bv_t2s,
        ln_spec_q_g, ln_spec_q_b, ln_spec_kv_g, ln_spec_kv_b,
        ln_spat_q_g, ln_spat_q_b, ln_spat_kv_g, ln_spat_kv_b);

    ln_qkv_kernel<<<dim3(BC, 4, 2), 256, SMEM_GEMM_BYTES>>>(x_spec, x_spat);

    attn_kernel<<<dim3(BC, HH, 2), 64>>>();

    out_kernel<<<dim3(BC, 2, 2), 256, SMEM_GEMM_BYTES>>>(
        x_spec, x_spat, Wo_s2t, bo_s2t, Wo_t2s, bo_t2s,
        gate_spec, gate_spat, out);
}

// round 2
// speedup vs baseline: 1.4448x; 1.4448x over previous
#include <cuda_runtime.h>
#include <cuda_bf16.h>
#include <cstdint>

// Problem constants
#define BB 8
#define SS 64
#define CC 128
#define DD 256
#define BC 1024              // BB*CC
#define TT 65536             // BC*SS tokens
#define HH 8
#define HD 32
#define KVH 4
#define BSCD 16777216        // BB*SS*CC*DD

// Scratch (allocation-free rule: __device__ globals)
__device__ float g_wfold[2][256 * 512];
__device__ float g_bfold[2][512];
__device__ float g_qkv[2ull * TT * 512];   // per token: [0:256)=Q, [256:384)=K, [384:512)=V
__device__ float g_att[2ull * TT * 256];   // pre-Wo attention output

__device__ __forceinline__ uint32_t f2tf32(float f) {
    uint32_t r;
    asm("cvt.rna.tf32.f32 %0, %1;" : "=r"(r) : "f"(f));
    return r;
}

__device__ __forceinline__ void mma_tf32(float c[4], const uint32_t a[4], const uint32_t b[2]) {
    asm volatile(
        "mma.sync.aligned.m16n8k8.row.col.f32.tf32.tf32.f32 "
        "{%0,%1,%2,%3}, {%4,%5,%6,%7}, {%8,%9}, {%0,%1,%2,%3};"
        : "+f"(c[0]), "+f"(c[1]), "+f"(c[2]), "+f"(c[3])
        : "r"(a[0]), "r"(a[1]), "r"(a[2]), "r"(a[3]), "r"(b[0]), "r"(b[1]));
}

// ---------------------------------------------------------------------------
// Kernel 1: fold LN gain/bias into QKV weights. grid (512,2), block 256.
// ---------------------------------------------------------------------------
__global__ __launch_bounds__(256) void fold_kernel(
    const float* __restrict__ Wq_s2t, const float* __restrict__ bq_s2t,
    const float* __restrict__ Wk_s2t, const float* __restrict__ bk_s2t,
    const float* __restrict__ Wv_s2t, const float* __restrict__ bv_s2t,
    const float* __restrict__ Wq_t2s, const float* __restrict__ bq_t2s,
    const float* __restrict__ Wk_t2s, const float* __restrict__ bk_t2s,
    const float* __restrict__ Wv_t2s, const float* __restrict__ bv_t2s,
    const float* __restrict__ g_spec_q, const float* __restrict__ b_spec_q,
    const float* __restrict__ g_spec_kv, const float* __restrict__ b_spec_kv,
    const float* __restrict__ g_spat_q, const float* __restrict__ b_spat_q,
    const float* __restrict__ g_spat_kv, const float* __restrict__ b_spat_kv)
{
    int n = blockIdx.x;      // output column in [0,512)
    int t = blockIdx.y;      // which input tensor
    int k = threadIdx.x;     // input dim in [0,256)

    const float *W, *g, *bln, *bbase;
    int nc, stride;
    if (t == 0) {
        if (n < 256)      { W = Wq_s2t; nc = n;       stride = 256; g = g_spec_q;  bln = b_spec_q;  bbase = bq_s2t; }
        else if (n < 384) { W = Wk_t2s; nc = n - 256; stride = 128; g = g_spec_kv; bln = b_spec_kv; bbase = bk_t2s; }
        else              { W = Wv_t2s; nc = n - 384; stride = 128; g = g_spec_kv; bln = b_spec_kv; bbase = bv_t2s; }
    } else {
        if (n < 256)      { W = Wq_t2s; nc = n;       stride = 256; g = g_spat_q;  bln = b_spat_q;  bbase = bq_t2s; }
        else if (n < 384) { W = Wk_s2t; nc = n - 256; stride = 128; g = g_spat_kv; bln = b_spat_kv; bbase = bk_s2t; }
        else              { W = Wv_s2t; nc = n - 384; stride = 128; g = g_spat_kv; bln = b_spat_kv; bbase = bv_s2t; }
    }

    float w = W[k * stride + nc];
    g_wfold[t][k * 512 + n] = g[k] * w;

    __shared__ float red[256];
    red[k] = bln[k] * w;
    __syncthreads();
    for (int o = 128; o > 0; o >>= 1) {
        if (k < o) red[k] += red[k + o];
        __syncthreads();
    }
    if (k == 0) g_bfold[t][n] = red[0] + bbase[nc];
}

// ---------------------------------------------------------------------------
// Kernel 2: fused LN-core + QKV projection, tf32 tensor cores.
// grid (512, 4, 2), block 256 (8 warps). Tile: M=128 (2 bc), N=128, K=256.
// smem: A tf32 [128][260] + W chunk transposed [128n][68] (K-chunk 64).
// ---------------------------------------------------------------------------
#define LNQKV_SMEM ((128 * 260 + 128 * 68) * 4)

__global__ __launch_bounds__(256) void ln_qkv_tc(
    const float* __restrict__ x_spec, const float* __restrict__ x_spat)
{
    int bc0 = blockIdx.x;     // pair of bc's
    int nt  = blockIdx.y;     // 128-col tile of 512
    int t   = blockIdx.z;
    const float* x = t ? x_spat : x_spec;

    extern __shared__ uint32_t smu[];
    uint32_t* As = smu;                 // [128][260] tf32 bits after LN
    uint32_t* Ws = smu + 128 * 260;     // [128 n][68] chunk, transposed
    float* Af = (float*)As;

    int tid = threadIdx.x;
    int wid = tid >> 5, lane = tid & 31;

    // Load x tile (128 tokens x 256)
    for (int i = tid; i < 128 * 256; i += 256) {
        int r = i >> 8, k = i & 255;
        int bc = bc0 * 2 + (r >> 6);
        int b = bc >> 7, c = bc & 127, s = r & 63;
        Af[r * 260 + k] = x[(((size_t)b * 64 + s) * 128 + c) * 256 + k];
    }
    __syncthreads();

    // LayerNorm core in place + convert to tf32: warp wid owns rows wid*16..+15
    for (int r = wid * 16; r < wid * 16 + 16; r++) {
        float s1 = 0.f, s2 = 0.f;
        #pragma unroll
        for (int k = lane; k < 256; k += 32) {
            float v = Af[r * 260 + k];
            s1 += v; s2 += v * v;
        }
        #pragma unroll
        for (int o = 16; o > 0; o >>= 1) {
            s1 += __shfl_xor_sync(0xffffffffu, s1, o);
            s2 += __shfl_xor_sync(0xffffffffu, s2, o);
        }
        float mu   = s1 * (1.f / 256.f);
        float rinv = rsqrtf(s2 * (1.f / 256.f) - mu * mu + 1e-5f);
        #pragma unroll
        for (int k = lane; k < 256; k += 32)
            As[r * 260 + k] = f2tf32((Af[r * 260 + k] - mu) * rinv);
    }
    __syncthreads();

    const float* Wf = g_wfold[t];
    int warp_m = wid >> 2, warp_n = wid & 3;
    int gid = lane >> 2, tig = lane & 3;

    float acc[4][4][4];
    #pragma unroll
    for (int ti = 0; ti < 4; ti++)
        #pragma unroll
        for (int tj = 0; tj < 4; tj++)
            #pragma unroll
            for (int q = 0; q < 4; q++) acc[ti][tj][q] = 0.f;

    for (int kc = 0; kc < 256; kc += 64) {
        // Load W chunk transposed [n][k], tf32
        for (int i = tid; i < 64 * 128; i += 256) {
            int kk = i >> 7, n = i & 127;
            Ws[n * 68 + kk] = f2tf32(Wf[(size_t)(kc + kk) * 512 + nt * 128 + n]);
        }
        __syncthreads();

        #pragma unroll
        for (int ks = 0; ks < 64; ks += 8) {
            uint32_t a[4][4], bfr[4][2];
            #pragma unroll
            for (int ti = 0; ti < 4; ti++) {
                const uint32_t* p = As + (warp_m * 64 + ti * 16 + gid) * 260 + kc + ks + tig;
                a[ti][0] = p[0];
                a[ti][1] = p[8 * 260];
                a[ti][2] = p[4];
                a[ti][3] = p[8 * 260 + 4];
            }
            #pragma unroll
            for (int tj = 0; tj < 4; tj++) {
                const uint32_t* p = Ws + (warp_n * 32 + tj * 8 + gid) * 68 + ks + tig;
                bfr[tj][0] = p[0];
                bfr[tj][1] = p[4];
            }
            #pragma unroll
            for (int ti = 0; ti < 4; ti++)
                #pragma unroll
                for (int tj = 0; tj < 4; tj++)
                    mma_tf32(acc[ti][tj], a[ti], bfr[tj]);
        }
        __syncthreads();
    }

    // Epilogue: + bias, write to g_qkv (token-major)
    float* out = g_qkv + (size_t)t * TT * 512 + (size_t)bc0 * 128 * 512;
    const float* bf = g_bfold[t] + nt * 128;
    #pragma unroll
    for (int ti = 0; ti < 4; ti++) {
        int r0 = warp_m * 64 + ti * 16 + gid;
        #pragma unroll
        for (int tj = 0; tj < 4; tj++) {
            int col = warp_n * 32 + tj * 8 + 2 * tig;
            float b0 = bf[col], b1 = bf[col + 1];
            float2 v0 = make_float2(acc[ti][tj][0] + b0, acc[ti][tj][1] + b1);
            float2 v1 = make_float2(acc[ti][tj][2] + b0, acc[ti][tj][3] + b1);
            *(float2*)(out + (size_t)r0 * 512 + nt * 128 + col) = v0;
            *(float2*)(out + (size_t)(r0 + 8) * 512 + nt * 128 + col) = v1;
        }
    }
}

// ---------------------------------------------------------------------------
// Kernel 3: attention per (bc, kvh, t): 2 query heads share K/V.
// 128 threads: thread = (head-half hh, query row). Scores in smem (no spill).
// ---------------------------------------------------------------------------
#define ATT_SMEM ((2 * 64 * 36 + 64 * 36 + 64 * 36 + 2 * 64 * 65) * 4)

__global__ __launch_bounds__(128) void attn_kernel()
{
    int bc = blockIdx.x, kvh = blockIdx.y, t = blockIdx.z;
    extern __shared__ float sf[];
    float* Qs = sf;                  // [2][64][36]
    float* Ks = sf + 2 * 64 * 36;    // [64][36]
    float* Vs = Ks + 64 * 36;        // [64][36]
    float* Ssm = Vs + 64 * 36;       // [2][64][65]

    int tid = threadIdx.x;
    const float* qb = g_qkv + (size_t)t * TT * 512 + (size_t)bc * 64 * 512;
    const float* kb = g_qkv + (size_t)(1 - t) * TT * 512 + (size_t)bc * 64 * 512;

    for (int i = tid; i < 2 * 64 * 32; i += 128) {
        int hh = i >> 11, r = (i >> 5) & 63, d = i & 31;
        Qs[(hh * 64 + r) * 36 + d] = qb[(size_t)r * 512 + (kvh * 2 + hh) * 32 + d];
    }
    for (int i = tid; i < 64 * 32; i += 128) {
        int r = i >> 5, d = i & 31;
        Ks[r * 36 + d] = kb[(size_t)r * 512 + 256 + kvh * 32 + d];
        Vs[r * 36 + d] = kb[(size_t)r * 512 + 384 + kvh * 32 + d];
    }
    __syncthreads();

    int hh = tid >> 6, row = tid & 63;
    const float scale = 0.17677669529663687f;  // 1/sqrt(32)

    float4 q[8];
    const float4* qp = (const float4*)(Qs + (hh * 64 + row) * 36);
    #pragma unroll
    for (int d4 = 0; d4 < 8; d4++) q[d4] = qp[d4];

    float* Srow = Ssm + (hh * 64 + row) * 65;
    float mx = -3.0e38f;
    for (int j = 0; j < 64; j++) {
        const float4* kp = (const float4*)(Ks + j * 36);
        float s = 0.f;
        #pragma unroll
        for (int d4 = 0; d4 < 8; d4++) {
            float4 kv = kp[d4];
            s += q[d4].x * kv.x + q[d4].y * kv.y + q[d4].z * kv.z + q[d4].w * kv.w;
        }
        s *= scale;
        Srow[j] = s;
        mx = fmaxf(mx, s);
    }
    float sum = 0.f;
    #pragma unroll
    for (int j = 0; j < 64; j++) {
        float e = __expf(Srow[j] - mx);
        Srow[j] = e;
        sum += e;
    }
    float rs = 1.f / sum;

    float4 o[8];
    #pragma unroll
    for (int d4 = 0; d4 < 8; d4++) o[d4] = make_float4(0.f, 0.f, 0.f, 0.f);
    for (int j = 0; j < 64; j++) {
        float p = Srow[j] * rs;
        const float4* vp = (const float4*)(Vs + j * 36);
        #pragma unroll
        for (int d4 = 0; d4 < 8; d4++) {
            float4 vv = vp[d4];
            o[d4].x += p * vv.x; o[d4].y += p * vv.y;
            o[d4].z += p * vv.z; o[d4].w += p * vv.w;
        }
    }

    float4* O = (float4*)(g_att + (size_t)t * TT * 256 +
                          ((size_t)bc * 64 + row) * 256 + (kvh * 2 + hh) * 32);
    #pragma unroll
    for (int d4 = 0; d4 < 8; d4++) O[d4] = o[d4];
}

// ---------------------------------------------------------------------------
// Kernel 4: output projection (tf32 TC) + bias + gate + residual + transpose.
// grid (512, 2, 2), block 256. M=128, N=128, K=256.
// ---------------------------------------------------------------------------
__global__ __launch_bounds__(256) void out_tc(
    const float* __restrict__ x_spec, const float* __restrict__ x_spat,
    const float* __restrict__ Wo_s2t, const float* __restrict__ bo_s2t,
    const float* __restrict__ Wo_t2s, const float* __restrict__ bo_t2s,
    const float* __restrict__ gate_spec, const float* __restrict__ gate_spat,
    float* __restrict__ d_out)
{
    int bc0 = blockIdx.x, nt = blockIdx.y, t = blockIdx.z;
    const float* A  = g_att + (size_t)t * TT * 256 + (size_t)bc0 * 128 * 256;
    const float* W  = t ? Wo_t2s : Wo_s2t;
    const float* bo = t ? bo_t2s : bo_s2t;
    const float* x  = t ? x_spat : x_spec;
    float gv = t ? gate_spat[0] : gate_spec[0];
    float gate = 1.f / (1.f + __expf(-gv));

    extern __shared__ uint32_t smu[];
    uint32_t* As = smu;                 // [128][260] tf32
    uint32_t* Ws = smu + 128 * 260;     // [128 n][68]

    int tid = threadIdx.x;
    int wid = tid >> 5, lane = tid & 31;

    for (int i = tid; i < 128 * 256; i += 256) {
        int r = i >> 8, k = i & 255;
        As[r * 260 + k] = f2tf32(A[(size_t)r * 256 + k]);
    }
    __syncthreads();

    int warp_m = wid >> 2, warp_n = wid & 3;
    int gid = lane >> 2, tig = lane & 3;

    float acc[4][4][4];
    #pragma unroll
    for (int ti = 0; ti < 4; ti++)
        #pragma unroll
        for (int tj = 0; tj < 4; tj++)
            #pragma unroll
            for (int q = 0; q < 4; q++) acc[ti][tj][q] = 0.f;

    for (int kc = 0; kc < 256; kc += 64) {
        for (int i = tid; i < 64 * 128; i += 256) {
            int kk = i >> 7, n = i & 127;
            Ws[n * 68 + kk] = f2tf32(W[(size_t)(kc + kk) * 256 + nt * 128 + n]);
        }
        __syncthreads();

        #pragma unroll
        for (int ks = 0; ks < 64; ks += 8) {
            uint32_t a[4][4], bfr[4][2];
            #pragma unroll
            for (int ti = 0; ti < 4; ti++) {
                const uint32_t* p = As + (warp_m * 64 + ti * 16 + gid) * 260 + kc + ks + tig;
                a[ti][0] = p[0];
                a[ti][1] = p[8 * 260];
                a[ti][2] = p[4];
                a[ti][3] = p[8 * 260 + 4];
            }
            #pragma unroll
            for (int tj = 0; tj < 4; tj++) {
                const uint32_t* p = Ws + (warp_n * 32 + tj * 8 + gid) * 68 + ks + tig;
                bfr[tj][0] = p[0];
                bfr[tj][1] = p[4];
            }
            #pragma unroll
            for (int ti = 0; ti < 4; ti++)
                #pragma unroll
                for (int tj = 0; tj < 4; tj++)
                    mma_tf32(acc[ti][tj], a[ti], bfr[tj]);
        }
        __syncthreads();
    }

    // Epilogue: bias + gate + residual, scatter back to (B,S,C,D) layout
    #pragma unroll
    for (int ti = 0; ti < 4; ti++) {
        #pragma unroll
        for (int half = 0; half < 2; half++) {
            int r = warp_m * 64 + ti * 16 + gid + half * 8;
            int bc = bc0 * 2 + (r >> 6);
            int s = r & 63, b = bc >> 7, c = bc & 127;
            size_t gb = (((size_t)b * 64 + s) * 128 + c) * 256 + nt * 128;
            #pragma unroll
            for (int tj = 0; tj < 4; tj++) {
                int col = warp_n * 32 + tj * 8 + 2 * tig;
                float b0 = bo[nt * 128 + col], b1 = bo[nt * 128 + col + 1];
                float a0 = acc[ti][tj][half * 2 + 0] + b0;
                float a1 = acc[ti][tj][half * 2 + 1] + b1;
                float2 xv = *(const float2*)(x + gb + col);
                float2 ov = make_float2(xv.x + gate * a0, xv.y + gate * a1);
                *(float2*)(d_out + (size_t)t * BSCD + gb + col) = ov;
            }
        }
    }
}

// ---------------------------------------------------------------------------
// Host launcher
// ---------------------------------------------------------------------------
extern "C" void kernel_launch(void* const* d_in, const int* in_sizes, int n_in,
                              void* d_out, int out_size)
{
    const float* x_spec      = (const float*)d_in[0];
    const float* x_spat      = (const float*)d_in[1];
    const float* ln_spec_q_g = (const float*)d_in[2];
    const float* ln_spec_q_b = (const float*)d_in[3];
    const float* ln_spec_kv_g= (const float*)d_in[4];
    const float* ln_spec_kv_b= (const float*)d_in[5];
    const float* ln_spat_q_g = (const float*)d_in[6];
    const float* ln_spat_q_b = (const float*)d_in[7];
    const float* ln_spat_kv_g= (const float*)d_in[8];
    const float* ln_spat_kv_b= (const float*)d_in[9];
    const float* Wq_s2t = (const float*)d_in[10];
    const float* bq_s2t = (const float*)d_in[11];
    const float* Wk_s2t = (const float*)d_in[12];
    const float* bk_s2t = (const float*)d_in[13];
    const float* Wv_s2t = (const float*)d_in[14];
    const float* bv_s2t = (const float*)d_in[15];
    const float* Wo_s2t = (const float*)d_in[16];
    const float* bo_s2t = (const float*)d_in[17];
    const float* Wq_t2s = (const float*)d_in[18];
    const float* bq_t2s = (const float*)d_in[19];
    const float* Wk_t2s = (const float*)d_in[20];
    const float* bk_t2s = (const float*)d_in[21];
    const float* Wv_t2s = (const float*)d_in[22];
    const float* bv_t2s = (const float*)d_in[23];
    const float* Wo_t2s = (const float*)d_in[24];
    const float* bo_t2s = (const float*)d_in[25];
    const float* gate_spec = (const float*)d_in[26];
    const float* gate_spat = (const float*)d_in[27];
    float* out = (float*)d_out;

    cudaFuncSetAttribute(ln_qkv_tc, cudaFuncAttributeMaxDynamicSharedMemorySize, LNQKV_SMEM);
    cudaFuncSetAttribute(out_tc,    cudaFuncAttributeMaxDynamicSharedMemorySize, LNQKV_SMEM);
    cudaFuncSetAttribute(attn_kernel, cudaFuncAttributeMaxDynamicSharedMemorySize, ATT_SMEM);

    fold_kernel<<<dim3(512, 2), 256>>>(
        Wq_s2t, bq_s2t, Wk_s2t, bk_s2t, Wv_s2t, bv_s2t,
        Wq_t2s, bq_t2s, Wk_t2s, bk_t2s, Wv_t2s, bv_t2s,
        ln_spec_q_g, ln_spec_q_b, ln_spec_kv_g, ln_spec_kv_b,
        ln_spat_q_g, ln_spat_q_b, ln_spat_kv_g, ln_spat_kv_b);

    ln_qkv_tc<<<dim3(512, 4, 2), 256, LNQKV_SMEM>>>(x_spec, x_spat);

    attn_kernel<<<dim3(BC, KVH, 2), 128, ATT_SMEM>>>();

    out_tc<<<dim3(512, 2, 2), 256, LNQKV_SMEM>>>(
        x_spec, x_spat, Wo_s2t, bo_s2t, Wo_t2s, bo_t2s,
        gate_spec, gate_spat, out);
}

// round 3
// speedup vs baseline: 3.9234x; 2.7155x over previous
#include <cuda_runtime.h>
#include <cstdint>

// Problem constants
#define SS 64
#define CC 128
#define DD 256
#define BC 1024
#define TT 65536             // BC*SS tokens
#define KVH 4
#define BSCD 16777216        // B*S*C*D

// Scratch (__device__ globals; allocation-free rule)
__device__ uint32_t g_wqkv[2][512 * 256];   // tf32 bits, [n][k] (LN-gain folded)
__device__ float    g_bfold[2][512];
__device__ uint32_t g_wo[2][256 * 256];     // tf32 bits, [n][k]
__device__ uint32_t g_qkv[2ull * TT * 512]; // tf32 bits; per token [Q 256|K 128|V 128]
__device__ uint32_t g_att[2ull * TT * 256]; // tf32 bits, pre-Wo attention output

__device__ __forceinline__ uint32_t f2tf32(float f) {
    uint32_t r;
    asm("cvt.rna.tf32.f32 %0, %1;" : "=r"(r) : "f"(f));
    return r;
}

__device__ __forceinline__ void mma_tf32(float c[4], const uint32_t a[4], const uint32_t b[2]) {
    asm volatile(
        "mma.sync.aligned.m16n8k8.row.col.f32.tf32.tf32.f32 "
        "{%0,%1,%2,%3}, {%4,%5,%6,%7}, {%8,%9}, {%0,%1,%2,%3};"
        : "+f"(c[0]), "+f"(c[1]), "+f"(c[2]), "+f"(c[3])
        : "r"(a[0]), "r"(a[1]), "r"(a[2]), "r"(a[3]), "r"(b[0]), "r"(b[1]));
}

__device__ __forceinline__ uint32_t smaddr(const void* p) {
    return (uint32_t)__cvta_generic_to_shared(p);
}
__device__ __forceinline__ void cp_async16(uint32_t dst, const void* src) {
    asm volatile("cp.async.cg.shared.global [%0], [%1], 16;" :: "r"(dst), "l"(src));
}
__device__ __forceinline__ void cp_commit() { asm volatile("cp.async.commit_group;"); }
__device__ __forceinline__ void cp_wait0()  { asm volatile("cp.async.wait_group 0;"); }
__device__ __forceinline__ void cp_wait1()  { asm volatile("cp.async.wait_group 1;"); }

// ---------------------------------------------------------------------------
// Kernel 1: prep. grid (768, 2), block 256.
//  n<512 : fold LN gain into QKV weight row n (tf32, transposed) + bias fold
//  n>=512: transpose+convert Wo row (n-512)
// ---------------------------------------------------------------------------
__global__ __launch_bounds__(256) void prep_kernel(
    const float* __restrict__ Wq_s2t, const float* __restrict__ bq_s2t,
    const float* __restrict__ Wk_s2t, const float* __restrict__ bk_s2t,
    const float* __restrict__ Wv_s2t, const float* __restrict__ bv_s2t,
    const float* __restrict__ Wq_t2s, const float* __restrict__ bq_t2s,
    const float* __restrict__ Wk_t2s, const float* __restrict__ bk_t2s,
    const float* __restrict__ Wv_t2s, const float* __restrict__ bv_t2s,
    const float* __restrict__ Wo_s2t, const float* __restrict__ Wo_t2s,
    const float* __restrict__ g_spec_q, const float* __restrict__ b_spec_q,
    const float* __restrict__ g_spec_kv, const float* __restrict__ b_spec_kv,
    const float* __restrict__ g_spat_q, const float* __restrict__ b_spat_q,
    const float* __restrict__ g_spat_kv, const float* __restrict__ b_spat_kv)
{
    int n = blockIdx.x, t = blockIdx.y, k = threadIdx.x;
    __shared__ float red[256];

    if (n < 512) {
        const float *W, *g, *bln, *bbase;
        int nc, stride;
        if (t == 0) {
            if (n < 256)      { W = Wq_s2t; nc = n;       stride = 256; g = g_spec_q;  bln = b_spec_q;  bbase = bq_s2t; }
            else if (n < 384) { W = Wk_t2s; nc = n - 256; stride = 128; g = g_spec_kv; bln = b_spec_kv; bbase = bk_t2s; }
            else              { W = Wv_t2s; nc = n - 384; stride = 128; g = g_spec_kv; bln = b_spec_kv; bbase = bv_t2s; }
        } else {
            if (n < 256)      { W = Wq_t2s; nc = n;       stride = 256; g = g_spat_q;  bln = b_spat_q;  bbase = bq_t2s; }
            else if (n < 384) { W = Wk_s2t; nc = n - 256; stride = 128; g = g_spat_kv; bln = b_spat_kv; bbase = bk_s2t; }
            else              { W = Wv_s2t; nc = n - 384; stride = 128; g = g_spat_kv; bln = b_spat_kv; bbase = bv_s2t; }
        }
        float w = W[k * stride + nc];
        g_wqkv[t][n * 256 + k] = f2tf32(g[k] * w);

        red[k] = bln[k] * w;
        __syncthreads();
        for (int o = 128; o > 0; o >>= 1) {
            if (k < o) red[k] += red[k + o];
            __syncthreads();
        }
        if (k == 0) g_bfold[t][n] = red[0] + bbase[nc];
    } else {
        int nc = n - 512;
        const float* Wo = t ? Wo_t2s : Wo_s2t;
        g_wo[t][nc * 256 + k] = f2tf32(Wo[k * 256 + nc]);
    }
}

// ---------------------------------------------------------------------------
// GEMM smem: A [128][260] tf32 + W double-buffered [2][256][36] tf32
// ---------------------------------------------------------------------------
#define GEMM_SMEM ((128 * 260 + 2 * 256 * 36) * 4)

// Kernel 2: fused LN + QKV projection. grid (512, 2, 2), block 512.
// M=128 (2 bc), N=256 (half of 512), K=256 in 8 chunks of 32, double-buffered.
__global__ __launch_bounds__(512) void ln_qkv_tc(
    const float* __restrict__ x_spec, const float* __restrict__ x_spat)
{
    int bc0 = blockIdx.x, nt = blockIdx.y, t = blockIdx.z;
    const float* x = t ? x_spat : x_spec;

    extern __shared__ uint32_t sm[];
    uint32_t* As = sm;                // [128][260]
    uint32_t* Ws = sm + 128 * 260;    // [2][256][36]
    float* Af = (float*)As;

    int tid = threadIdx.x, wid = tid >> 5, lane = tid & 31;
    int gid = lane >> 2, tig = lane & 3;

    // A tile via cp.async: 128 rows x 64 16B-units
    #pragma unroll
    for (int it = 0; it < 16; it++) {
        int idx = tid + it * 512;
        int r = idx >> 6, u = idx & 63;
        int bc = bc0 * 2 + (r >> 6);
        int b = bc >> 7, c = bc & 127, s = r & 63;
        const float* src = x + (((size_t)b * 64 + s) * 128 + c) * 256 + u * 4;
        cp_async16(smaddr(As + r * 260 + u * 4), src);
    }
    cp_commit();

    const uint32_t* Wg = g_wqkv[t] + (size_t)nt * 256 * 256;
    // W chunk 0
    #pragma unroll
    for (int it = 0; it < 4; it++) {
        int idx = tid + it * 512;
        int r = idx >> 3, u = idx & 7;
        cp_async16(smaddr(Ws + r * 36 + u * 4), Wg + r * 256 + u * 4);
    }
    cp_commit();
    cp_wait0();
    __syncthreads();

    // LayerNorm core in place + tf32 convert: 16 warps x 8 rows
    #pragma unroll
    for (int rr = 0; rr < 8; rr++) {
        int r = wid * 8 + rr;
        float s1 = 0.f, s2 = 0.f;
        #pragma unroll
        for (int k = lane; k < 256; k += 32) {
            float v = Af[r * 260 + k];
            s1 += v; s2 += v * v;
        }
        #pragma unroll
        for (int o = 16; o > 0; o >>= 1) {
            s1 += __shfl_xor_sync(0xffffffffu, s1, o);
            s2 += __shfl_xor_sync(0xffffffffu, s2, o);
        }
        float mu   = s1 * (1.f / 256.f);
        float rinv = rsqrtf(s2 * (1.f / 256.f) - mu * mu + 1e-5f);
        #pragma unroll
        for (int k = lane; k < 256; k += 32)
            As[r * 260 + k] = f2tf32((Af[r * 260 + k] - mu) * rinv);
    }
    __syncthreads();

    int warp_m = wid >> 2, warp_n = wid & 3;
    float acc[2][8][4];
    #pragma unroll
    for (int ti = 0; ti < 2; ti++)
        #pragma unroll
        for (int tj = 0; tj < 8; tj++)
            #pragma unroll
            for (int q = 0; q < 4; q++) acc[ti][tj][q] = 0.f;

    #pragma unroll
    for (int c = 0; c < 8; c++) {
        if (c < 7) {
            int buf = (c + 1) & 1;
            #pragma unroll
            for (int it = 0; it < 4; it++) {
                int idx = tid + it * 512;
                int r = idx >> 3, u = idx & 7;
                cp_async16(smaddr(Ws + buf * 256 * 36 + r * 36 + u * 4),
                           Wg + r * 256 + (c + 1) * 32 + u * 4);
            }
            cp_commit();
            cp_wait1();
        } else {
            cp_wait0();
        }
        __syncthreads();

        const uint32_t* Wb = Ws + (c & 1) * 256 * 36;
        #pragma unroll
        for (int ks = 0; ks < 32; ks += 8) {
            int kg = c * 32 + ks;
            uint32_t a[2][4], bf[8][2];
            #pragma unroll
            for (int ti = 0; ti < 2; ti++) {
                const uint32_t* p = As + (warp_m * 32 + ti * 16 + gid) * 260 + kg + tig;
                a[ti][0] = p[0];
                a[ti][1] = p[8 * 260];
                a[ti][2] = p[4];
                a[ti][3] = p[8 * 260 + 4];
            }
            #pragma unroll
            for (int tj = 0; tj < 8; tj++) {
                const uint32_t* p = Wb + (warp_n * 64 + tj * 8 + gid) * 36 + ks + tig;
                bf[tj][0] = p[0];
                bf[tj][1] = p[4];
            }
            #pragma unroll
            for (int ti = 0; ti < 2; ti++)
                #pragma unroll
                for (int tj = 0; tj < 8; tj++)
                    mma_tf32(acc[ti][tj], a[ti], bf[tj]);
        }
        __syncthreads();
    }

    // Epilogue: + bias, write tf32 bits to g_qkv
    uint32_t* out = g_qkv + (size_t)t * TT * 512 + (size_t)bc0 * 128 * 512 + nt * 256;
    const float* bfo = g_bfold[t] + nt * 256;
    #pragma unroll
    for (int ti = 0; ti < 2; ti++) {
        int r0 = warp_m * 32 + ti * 16 + gid;
        #pragma unroll
        for (int tj = 0; tj < 8; tj++) {
            int col = warp_n * 64 + tj * 8 + 2 * tig;
            float b0 = bfo[col], b1 = bfo[col + 1];
            uint2 v0 = make_uint2(f2tf32(acc[ti][tj][0] + b0), f2tf32(acc[ti][tj][1] + b1));
            uint2 v1 = make_uint2(f2tf32(acc[ti][tj][2] + b0), f2tf32(acc[ti][tj][3] + b1));
            *(uint2*)(out + (size_t)r0 * 512 + col) = v0;
            *(uint2*)(out + (size_t)(r0 + 8) * 512 + col) = v1;
        }
    }
}

// ---------------------------------------------------------------------------
// Kernel 3: tensor-core attention. grid (1024, 4, 2), block 128 (4 warps).
// Per block: 2 query heads sharing one KV head. QK^T and PV as tf32 mma.
// ---------------------------------------------------------------------------
#define ATT_SMEM ((2 * 64 * 36 + 64 * 36 + 32 * 68 + 2 * 64 * 68) * 4)

__global__ __launch_bounds__(128) void attn_tc()
{
    int bc = blockIdx.x, kvh = blockIdx.y, t = blockIdx.z;
    extern __shared__ uint32_t smu[];
    uint32_t* Qs = smu;                          // [2][64][36] tf32
    uint32_t* Ks = Qs + 2 * 64 * 36;             // [64][36]
    uint32_t* Vt = Ks + 64 * 36;                 // [32][68] transposed (d-major)
    float*    S  = (float*)(Vt + 32 * 68);       // [2][64][68] scores / probs(tf32 bits)
    uint32_t* Su = (uint32_t*)S;

    int tid = threadIdx.x, wid = tid >> 5, lane = tid & 31;
    int gid = lane >> 2, tig = lane & 3;

    const uint32_t* qb = g_qkv + (size_t)t * TT * 512 + (size_t)bc * 64 * 512;
    const uint32_t* kb = g_qkv + (size_t)(1 - t) * TT * 512 + (size_t)bc * 64 * 512;

    for (int i = tid; i < 2 * 64 * 32; i += 128) {
        int hh = i >> 11, r = (i >> 5) & 63, d = i & 31;
        Qs[(hh * 64 + r) * 36 + d] = qb[(size_t)r * 512 + (kvh * 2 + hh) * 32 + d];
    }
    for (int i = tid; i < 64 * 32; i += 128) {
        int r = (i >> 5), d = i & 31;
        Ks[r * 36 + d] = kb[(size_t)r * 512 + 256 + kvh * 32 + d];
        Vt[d * 68 + r] = kb[(size_t)r * 512 + 384 + kvh * 32 + d];
    }
    __syncthreads();

    int hh = wid >> 1, mh = wid & 1;   // warp: head-half, m-half (32 rows)
    const float scale = 0.17677669529663687f;  // 1/sqrt(32)

    // QK^T: M=32 (2 m16), N=64 (8 n8), K=32
    {
        float acc[2][8][4];
        #pragma unroll
        for (int ti = 0; ti < 2; ti++)
            #pragma unroll
            for (int tj = 0; tj < 8; tj++)
                #pragma unroll
                for (int q = 0; q < 4; q++) acc[ti][tj][q] = 0.f;

        #pragma unroll
        for (int ks = 0; ks < 32; ks += 8) {
            uint32_t a[2][4], bf[8][2];
            #pragma unroll
            for (int ti = 0; ti < 2; ti++) {
                const uint32_t* p = Qs + (hh * 64 + mh * 32 + ti * 16 + gid) * 36 + ks + tig;
                a[ti][0] = p[0]; a[ti][1] = p[8 * 36]; a[ti][2] = p[4]; a[ti][3] = p[8 * 36 + 4];
            }
            #pragma unroll
            for (int tj = 0; tj < 8; tj++) {
                const uint32_t* p = Ks + (tj * 8 + gid) * 36 + ks + tig;
                bf[tj][0] = p[0]; bf[tj][1] = p[4];
            }
            #pragma unroll
            for (int ti = 0; ti < 2; ti++)
                #pragma unroll
                for (int tj = 0; tj < 8; tj++)
                    mma_tf32(acc[ti][tj], a[ti], bf[tj]);
        }
        // scores -> smem (scaled)
        #pragma unroll
        for (int ti = 0; ti < 2; ti++) {
            int r0 = hh * 64 + mh * 32 + ti * 16 + gid;
            #pragma unroll
            for (int tj = 0; tj < 8; tj++) {
                int col = tj * 8 + 2 * tig;
                *(float2*)(S + (size_t)r0 * 68 + col) =
                    make_float2(acc[ti][tj][0] * scale, acc[ti][tj][1] * scale);
                *(float2*)(S + (size_t)(r0 + 8) * 68 + col) =
                    make_float2(acc[ti][tj][2] * scale, acc[ti][tj][3] * scale);
            }
        }
    }
    __syncthreads();

    // Softmax: one row per thread (128 rows), write probs back as tf32 bits
    {
        float* row = S + (size_t)tid * 68;
        float mx = -3.0e38f;
        #pragma unroll
        for (int j = 0; j < 64; j++) mx = fmaxf(mx, row[j]);
        float sum = 0.f;
        float e[64];
        #pragma unroll
        for (int j = 0; j < 64; j++) { e[j] = __expf(row[j] - mx); sum += e[j]; }
        float rs = 1.f / sum;
        uint32_t* urow = (uint32_t*)row;
        #pragma unroll
        for (int j = 0; j < 64; j++) urow[j] = f2tf32(e[j] * rs);
    }
    __syncthreads();

    // PV: M=32 (2 m16), N=32 (4 n8), K=64
    {
        float acc[2][4][4];
        #pragma unroll
        for (int ti = 0; ti < 2; ti++)
            #pragma unroll
            for (int tj = 0; tj < 4; tj++)
                #pragma unroll
                for (int q = 0; q < 4; q++) acc[ti][tj][q] = 0.f;

        #pragma unroll
        for (int ks = 0; ks < 64; ks += 8) {
            uint32_t a[2][4], bf[4][2];
            #pragma unroll
            for (int ti = 0; ti < 2; ti++) {
                const uint32_t* p = Su + (size_t)(hh * 64 + mh * 32 + ti * 16 + gid) * 68 + ks + tig;
                a[ti][0] = p[0]; a[ti][1] = p[8 * 68]; a[ti][2] = p[4]; a[ti][3] = p[8 * 68 + 4];
            }
            #pragma unroll
            for (int tj = 0; tj < 4; tj++) {
                const uint32_t* p = Vt + (tj * 8 + gid) * 68 + ks + tig;
                bf[tj][0] = p[0]; bf[tj][1] = p[4];
            }
            #pragma unroll
            for (int ti = 0; ti < 2; ti++)
                #pragma unroll
                for (int tj = 0; tj < 4; tj++)
                    mma_tf32(acc[ti][tj], a[ti], bf[tj]);
        }

        // write attention output (tf32 bits) to g_att
        uint32_t* O = g_att + (size_t)t * TT * 256 + (size_t)bc * 64 * 256 + (kvh * 2 + hh) * 32;
        #pragma unroll
        for (int ti = 0; ti < 2; ti++) {
            int r0 = mh * 32 + ti * 16 + gid;
            #pragma unroll
            for (int tj = 0; tj < 4; tj++) {
                int col = tj * 8 + 2 * tig;
                uint2 v0 = make_uint2(f2tf32(acc[ti][tj][0]), f2tf32(acc[ti][tj][1]));
                uint2 v1 = make_uint2(f2tf32(acc[ti][tj][2]), f2tf32(acc[ti][tj][3]));
                *(uint2*)(O + (size_t)r0 * 256 + col) = v0;
                *(uint2*)(O + (size_t)(r0 + 8) * 256 + col) = v1;
            }
        }
    }
}

// ---------------------------------------------------------------------------
// Kernel 4: output projection + bias + gate + residual + transpose-back.
// grid (512, 2), block 512. M=128, N=256, K=256 in 8 chunks, double-buffered.
// ---------------------------------------------------------------------------
__global__ __launch_bounds__(512) void out_tc(
    const float* __restrict__ x_spec, const float* __restrict__ x_spat,
    const float* __restrict__ bo_s2t, const float* __restrict__ bo_t2s,
    const float* __restrict__ gate_spec, const float* __restrict__ gate_spat,
    float* __restrict__ d_out)
{
    int bc0 = blockIdx.x, t = blockIdx.y;
    const float* bo = t ? bo_t2s : bo_s2t;
    const float* x  = t ? x_spat : x_spec;
    float gv = t ? gate_spat[0] : gate_spec[0];
    float gate = 1.f / (1.f + __expf(-gv));

    extern __shared__ uint32_t sm[];
    uint32_t* As = sm;               // [128][260]
    uint32_t* Ws = sm + 128 * 260;   // [2][256][36]

    int tid = threadIdx.x, wid = tid >> 5, lane = tid & 31;
    int gid = lane >> 2, tig = lane & 3;

    // A tile (already tf32 bits) via cp.async
    const uint32_t* A = g_att + (size_t)t * TT * 256 + (size_t)bc0 * 128 * 256;
    #pragma unroll
    for (int it = 0; it < 16; it++) {
        int idx = tid + it * 512;
        int r = idx >> 6, u = idx & 63;
        cp_async16(smaddr(As + r * 260 + u * 4), A + (size_t)r * 256 + u * 4);
    }
    cp_commit();

    const uint32_t* Wg = g_wo[t];
    #pragma unroll
    for (int it = 0; it < 4; it++) {
        int idx = tid + it * 512;
        int r = idx >> 3, u = idx & 7;
        cp_async16(smaddr(Ws + r * 36 + u * 4), Wg + r * 256 + u * 4);
    }
    cp_commit();
    cp_wait0();
    __syncthreads();

    int warp_m = wid >> 2, warp_n = wid & 3;
    float acc[2][8][4];
    #pragma unroll
    for (int ti = 0; ti < 2; ti++)
        #pragma unroll
        for (int tj = 0; tj < 8; tj++)
            #pragma unroll
            for (int q = 0; q < 4; q++) acc[ti][tj][q] = 0.f;

    #pragma unroll
    for (int c = 0; c < 8; c++) {
        if (c < 7) {
            int buf = (c + 1) & 1;
            #pragma unroll
            for (int it = 0; it < 4; it++) {
                int idx = tid + it * 512;
                int r = idx >> 3, u = idx & 7;
                cp_async16(smaddr(Ws + buf * 256 * 36 + r * 36 + u * 4),
                           Wg + r * 256 + (c + 1) * 32 + u * 4);
            }
            cp_commit();
            cp_wait1();
        } else {
            cp_wait0();
        }
        __syncthreads();

        const uint32_t* Wb = Ws + (c & 1) * 256 * 36;
        #pragma unroll
        for (int ks = 0; ks < 32; ks += 8) {
            int kg = c * 32 + ks;
            uint32_t a[2][4], bf[8][2];
            #pragma unroll
            for (int ti = 0; ti < 2; ti++) {
                const uint32_t* p = As + (warp_m * 32 + ti * 16 + gid) * 260 + kg + tig;
                a[ti][0] = p[0];
                a[ti][1] = p[8 * 260];
                a[ti][2] = p[4];
                a[ti][3] = p[8 * 260 + 4];
            }
            #pragma unroll
            for (int tj = 0; tj < 8; tj++) {
                const uint32_t* p = Wb + (warp_n * 64 + tj * 8 + gid) * 36 + ks + tig;
                bf[tj][0] = p[0]; bf[tj][1] = p[4];
            }
            #pragma unroll
            for (int ti = 0; ti < 2; ti++)
                #pragma unroll
                for (int tj = 0; tj < 8; tj++)
                    mma_tf32(acc[ti][tj], a[ti], bf[tj]);
        }
        __syncthreads();
    }

    // Epilogue: bias + gate + residual, scatter back to (B,S,C,D)
    #pragma unroll
    for (int ti = 0; ti < 2; ti++) {
        #pragma unroll
        for (int half = 0; half < 2; half++) {
            int r = warp_m * 32 + ti * 16 + gid + half * 8;
            int bc = bc0 * 2 + (r >> 6);
            int s = r & 63, b = bc >> 7, c = bc & 127;
            size_t gb = (((size_t)b * 64 + s) * 128 + c) * 256;
            #pragma unroll
            for (int tj = 0; tj < 8; tj++) {
                int col = warp_n * 64 + tj * 8 + 2 * tig;
                float a0 = acc[ti][tj][half * 2 + 0] + bo[col];
                float a1 = acc[ti][tj][half * 2 + 1] + bo[col + 1];
                float2 xv = *(const float2*)(x + gb + col);
                float2 ov = make_float2(xv.x + gate * a0, xv.y + gate * a1);
                *(float2*)(d_out + (size_t)t * BSCD + gb + col) = ov;
            }
        }
    }
}

// ---------------------------------------------------------------------------
// Host launcher
// ---------------------------------------------------------------------------
extern "C" void kernel_launch(void* const* d_in, const int* in_sizes, int n_in,
                              void* d_out, int out_size)
{
    const float* x_spec      = (const float*)d_in[0];
    const float* x_spat      = (const float*)d_in[1];
    const float* ln_spec_q_g = (const float*)d_in[2];
    const float* ln_spec_q_b = (const float*)d_in[3];
    const float* ln_spec_kv_g= (const float*)d_in[4];
    const float* ln_spec_kv_b= (const float*)d_in[5];
    const float* ln_spat_q_g = (const float*)d_in[6];
    const float* ln_spat_q_b = (const float*)d_in[7];
    const float* ln_spat_kv_g= (const float*)d_in[8];
    const float* ln_spat_kv_b= (const float*)d_in[9];
    const float* Wq_s2t = (const float*)d_in[10];
    const float* bq_s2t = (const float*)d_in[11];
    const float* Wk_s2t = (const float*)d_in[12];
    const float* bk_s2t = (const float*)d_in[13];
    const float* Wv_s2t = (const float*)d_in[14];
    const float* bv_s2t = (const float*)d_in[15];
    const float* Wo_s2t = (const float*)d_in[16];
    const float* bo_s2t = (const float*)d_in[17];
    const float* Wq_t2s = (const float*)d_in[18];
    const float* bq_t2s = (const float*)d_in[19];
    const float* Wk_t2s = (const float*)d_in[20];
    const float* bk_t2s = (const float*)d_in[21];
    const float* Wv_t2s = (const float*)d_in[22];
    const float* bv_t2s = (const float*)d_in[23];
    const float* Wo_t2s = (const float*)d_in[24];
    const float* bo_t2s = (const float*)d_in[25];
    const float* gate_spec = (const float*)d_in[26];
    const float* gate_spat = (const float*)d_in[27];
    float* out = (float*)d_out;

    cudaFuncSetAttribute(ln_qkv_tc, cudaFuncAttributeMaxDynamicSharedMemorySize, GEMM_SMEM);
    cudaFuncSetAttribute(out_tc,    cudaFuncAttributeMaxDynamicSharedMemorySize, GEMM_SMEM);
    cudaFuncSetAttribute(attn_tc,   cudaFuncAttributeMaxDynamicSharedMemorySize, ATT_SMEM);

    prep_kernel<<<dim3(768, 2), 256>>>(
        Wq_s2t, bq_s2t, Wk_s2t, bk_s2t, Wv_s2t, bv_s2t,
        Wq_t2s, bq_t2s, Wk_t2s, bk_t2s, Wv_t2s, bv_t2s,
        Wo_s2t, Wo_t2s,
        ln_spec_q_g, ln_spec_q_b, ln_spec_kv_g, ln_spec_kv_b,
        ln_spat_q_g, ln_spat_q_b, ln_spat_kv_g, ln_spat_kv_b);

    ln_qkv_tc<<<dim3(512, 2, 2), 512, GEMM_SMEM>>>(x_spec, x_spat);

    attn_tc<<<dim3(1024, 4, 2), 128, ATT_SMEM>>>();

    out_tc<<<dim3(512, 2), 512, GEMM_SMEM>>>(
        x_spec, x_spat, bo_s2t, bo_t2s, gate_spec, gate_spat, out);
}

// round 4
// speedup vs baseline: 8.6061x; 2.1935x over previous
#include <cuda_runtime.h>
#include <cuda_bf16.h>
#include <cstdint>

// Problem constants
#define SS 64
#define CC 128
#define DD 256
#define BC 1024
#define TT 65536             // BC*SS tokens
#define KVH 4
#define BSCD 16777216        // B*S*C*D

// Scratch (__device__ globals; allocation-free rule)
__device__ __nv_bfloat16 g_wqkv[2][512 * 256];   // [n][k] bf16 (LN-gain folded)
__device__ float         g_bfold[2][512];
__device__ __nv_bfloat16 g_wo[2][256 * 256];     // [n][k] bf16
__device__ __nv_bfloat16 g_qkv[2ull * TT * 512]; // per token [Q 256|K 128|V 128]
__device__ __nv_bfloat16 g_att[2ull * TT * 256]; // pre-Wo attention output

__device__ __forceinline__ uint32_t pack_bf16(float lo, float hi) {
    __nv_bfloat162 h = __floats2bfloat162_rn(lo, hi);
    return *reinterpret_cast<uint32_t*>(&h);
}

__device__ __forceinline__ void mma_bf16(float c[4], const uint32_t a[4], const uint32_t b[2]) {
    asm volatile(
        "mma.sync.aligned.m16n8k16.row.col.f32.bf16.bf16.f32 "
        "{%0,%1,%2,%3}, {%4,%5,%6,%7}, {%8,%9}, {%0,%1,%2,%3};"
        : "+f"(c[0]), "+f"(c[1]), "+f"(c[2]), "+f"(c[3])
        : "r"(a[0]), "r"(a[1]), "r"(a[2]), "r"(a[3]), "r"(b[0]), "r"(b[1]));
}

__device__ __forceinline__ void ldsm4(uint32_t& r0, uint32_t& r1, uint32_t& r2, uint32_t& r3,
                                      uint32_t addr) {
    asm volatile("ldmatrix.sync.aligned.m8n8.x4.shared.b16 {%0,%1,%2,%3}, [%4];"
                 : "=r"(r0), "=r"(r1), "=r"(r2), "=r"(r3) : "r"(addr));
}

__device__ __forceinline__ uint32_t smaddr(const void* p) {
    return (uint32_t)__cvta_generic_to_shared(p);
}
__device__ __forceinline__ void cp_async16(uint32_t dst, const void* src) {
    asm volatile("cp.async.cg.shared.global [%0], [%1], 16;" :: "r"(dst), "l"(src));
}
__device__ __forceinline__ void cp_commit() { asm volatile("cp.async.commit_group;"); }
__device__ __forceinline__ void cp_wait0()  { asm volatile("cp.async.wait_group 0;"); }
__device__ __forceinline__ void cp_wait1()  { asm volatile("cp.async.wait_group 1;"); }

// A tile pitch (halves): 256 + 8 pad -> rows 528B apart (4 banks) => ldmatrix clean
#define AP 264
// W chunk pitch (halves): 64 + 8
#define WP 72

// ---------------------------------------------------------------------------
// Kernel 1: prep. grid (768, 2), block 256.
// ---------------------------------------------------------------------------
__global__ __launch_bounds__(256) void prep_kernel(
    const float* __restrict__ Wq_s2t, const float* __restrict__ bq_s2t,
    const float* __restrict__ Wk_s2t, const float* __restrict__ bk_s2t,
    const float* __restrict__ Wv_s2t, const float* __restrict__ bv_s2t,
    const float* __restrict__ Wq_t2s, const float* __restrict__ bq_t2s,
    const float* __restrict__ Wk_t2s, const float* __restrict__ bk_t2s,
    const float* __restrict__ Wv_t2s, const float* __restrict__ bv_t2s,
    const float* __restrict__ Wo_s2t, const float* __restrict__ Wo_t2s,
    const float* __restrict__ g_spec_q, const float* __restrict__ b_spec_q,
    const float* __restrict__ g_spec_kv, const float* __restrict__ b_spec_kv,
    const float* __restrict__ g_spat_q, const float* __restrict__ b_spat_q,
    const float* __restrict__ g_spat_kv, const float* __restrict__ b_spat_kv)
{
    int n = blockIdx.x, t = blockIdx.y, k = threadIdx.x;
    __shared__ float red[256];

    if (n < 512) {
        const float *W, *g, *bln, *bbase;
        int nc, stride;
        if (t == 0) {
            if (n < 256)      { W = Wq_s2t; nc = n;       stride = 256; g = g_spec_q;  bln = b_spec_q;  bbase = bq_s2t; }
            else if (n < 384) { W = Wk_t2s; nc = n - 256; stride = 128; g = g_spec_kv; bln = b_spec_kv; bbase = bk_t2s; }
            else              { W = Wv_t2s; nc = n - 384; stride = 128; g = g_spec_kv; bln = b_spec_kv; bbase = bv_t2s; }
        } else {
            if (n < 256)      { W = Wq_t2s; nc = n;       stride = 256; g = g_spat_q;  bln = b_spat_q;  bbase = bq_t2s; }
            else if (n < 384) { W = Wk_s2t; nc = n - 256; stride = 128; g = g_spat_kv; bln = b_spat_kv; bbase = bk_s2t; }
            else              { W = Wv_s2t; nc = n - 384; stride = 128; g = g_spat_kv; bln = b_spat_kv; bbase = bv_s2t; }
        }
        float w = W[k * stride + nc];
        g_wqkv[t][n * 256 + k] = __float2bfloat16(g[k] * w);

        red[k] = bln[k] * w;
        __syncthreads();
        for (int o = 128; o > 0; o >>= 1) {
            if (k < o) red[k] += red[k + o];
            __syncthreads();
        }
        if (k == 0) g_bfold[t][n] = red[0] + bbase[nc];
    } else {
        int nc = n - 512;
        const float* Wo = t ? Wo_t2s : Wo_s2t;
        g_wo[t][nc * 256 + k] = __float2bfloat16(Wo[k * 256 + nc]);
    }
}

// ---------------------------------------------------------------------------
// GEMM smem: A bf16 [128][AP] + W bf16 [2][256][WP]
// ---------------------------------------------------------------------------
#define GEMM_SMEM ((128 * AP + 2 * 256 * WP) * 2)

// Kernel 2: fused LN + QKV projection. grid (512, 2, 2), block 512.
// M=128 (2 bc), N=256, K=256 in 4 chunks of 64, double-buffered cp.async.
__global__ __launch_bounds__(512) void ln_qkv_tc(
    const float* __restrict__ x_spec, const float* __restrict__ x_spat)
{
    int bc0 = blockIdx.x, nt = blockIdx.y, t = blockIdx.z;
    const float* x = t ? x_spat : x_spec;

    extern __shared__ __nv_bfloat16 smb[];
    __nv_bfloat16* As = smb;               // [128][AP]
    __nv_bfloat16* Ws = smb + 128 * AP;    // [2][256][WP]

    int tid = threadIdx.x, wid = tid >> 5, lane = tid & 31;
    const __nv_bfloat16* Wg = g_wqkv[t] + (size_t)nt * 256 * 256;

    // prefetch W chunk 0
    #pragma unroll
    for (int it = 0; it < 4; it++) {
        int idx = tid + it * 512;
        int n = idx >> 3, u = idx & 7;
        cp_async16(smaddr(Ws + n * WP + u * 8), Wg + n * 256 + u * 8);
    }
    cp_commit();

    // LayerNorm in registers -> bf16 A tile
    #pragma unroll 2
    for (int rr = 0; rr < 8; rr++) {
        int r = wid * 8 + rr;
        int bc = bc0 * 2 + (r >> 6), b = bc >> 7, c = bc & 127, s = r & 63;
        const float* src = x + (((size_t)b * 64 + s) * 128 + c) * 256 + lane * 8;
        float4 v0 = *(const float4*)src;
        float4 v1 = *(const float4*)(src + 4);
        float s1 = v0.x + v0.y + v0.z + v0.w + v1.x + v1.y + v1.z + v1.w;
        float s2 = v0.x*v0.x + v0.y*v0.y + v0.z*v0.z + v0.w*v0.w
                 + v1.x*v1.x + v1.y*v1.y + v1.z*v1.z + v1.w*v1.w;
        #pragma unroll
        for (int o = 16; o > 0; o >>= 1) {
            s1 += __shfl_xor_sync(0xffffffffu, s1, o);
            s2 += __shfl_xor_sync(0xffffffffu, s2, o);
        }
        float mu = s1 * (1.f / 256.f);
        float rinv = rsqrtf(s2 * (1.f / 256.f) - mu * mu + 1e-5f);
        uint4 pk;
        pk.x = pack_bf16((v0.x - mu) * rinv, (v0.y - mu) * rinv);
        pk.y = pack_bf16((v0.z - mu) * rinv, (v0.w - mu) * rinv);
        pk.z = pack_bf16((v1.x - mu) * rinv, (v1.y - mu) * rinv);
        pk.w = pack_bf16((v1.z - mu) * rinv, (v1.w - mu) * rinv);
        *(uint4*)(As + r * AP + lane * 8) = pk;
    }
    __syncthreads();

    int warp_m = wid >> 2, warp_n = wid & 3;
    int gid = lane >> 2, tig = lane & 3;

    uint32_t a_addr[2], b_addr[4];
    #pragma unroll
    for (int ti = 0; ti < 2; ti++)
        a_addr[ti] = smaddr(As) +
            (((warp_m * 32 + ti * 16 + (lane & 15)) * AP + ((lane >> 4) << 3)) << 1);
    #pragma unroll
    for (int tg = 0; tg < 4; tg++)
        b_addr[tg] = smaddr(Ws) +
            (((warp_n * 64 + tg * 16 + ((lane >> 4) << 3) + (lane & 7)) * WP +
              (((lane >> 3) & 1) << 3)) << 1);

    float acc[2][8][4];
    #pragma unroll
    for (int ti = 0; ti < 2; ti++)
        #pragma unroll
        for (int tj = 0; tj < 8; tj++)
            #pragma unroll
            for (int q = 0; q < 4; q++) acc[ti][tj][q] = 0.f;

    #pragma unroll
    for (int c = 0; c < 4; c++) {
        if (c < 3) {
            int buf = (c + 1) & 1;
            #pragma unroll
            for (int it = 0; it < 4; it++) {
                int idx = tid + it * 512;
                int n = idx >> 3, u = idx & 7;
                cp_async16(smaddr(Ws + buf * 256 * WP + n * WP + u * 8),
                           Wg + n * 256 + (c + 1) * 64 + u * 8);
            }
            cp_commit();
            cp_wait1();
        } else {
            cp_wait0();
        }
        __syncthreads();

        uint32_t wboff = ((c & 1) * 256 * WP) << 1;
        #pragma unroll
        for (int ksi = 0; ksi < 4; ksi++) {
            int kg = c * 64 + ksi * 16;
            uint32_t a[2][4], bfr[8][2];
            #pragma unroll
            for (int ti = 0; ti < 2; ti++)
                ldsm4(a[ti][0], a[ti][1], a[ti][2], a[ti][3], a_addr[ti] + (kg << 1));
            #pragma unroll
            for (int tg = 0; tg < 4; tg++)
                ldsm4(bfr[2*tg][0], bfr[2*tg][1], bfr[2*tg+1][0], bfr[2*tg+1][1],
                      b_addr[tg] + wboff + (ksi << 5));
            #pragma unroll
            for (int ti = 0; ti < 2; ti++)
                #pragma unroll
                for (int tj = 0; tj < 8; tj++)
                    mma_bf16(acc[ti][tj], a[ti], bfr[tj]);
        }
        __syncthreads();
    }

    // Epilogue: + bias, bf16 -> g_qkv
    __nv_bfloat16* out = g_qkv + (size_t)t * TT * 512 + (size_t)bc0 * 128 * 512 + nt * 256;
    const float* bfo = g_bfold[t] + nt * 256;
    #pragma unroll
    for (int ti = 0; ti < 2; ti++) {
        int r0 = warp_m * 32 + ti * 16 + gid;
        #pragma unroll
        for (int tj = 0; tj < 8; tj++) {
            int col = warp_n * 64 + tj * 8 + 2 * tig;
            float b0 = bfo[col], b1 = bfo[col + 1];
            *(uint32_t*)(out + (size_t)r0 * 512 + col)       = pack_bf16(acc[ti][tj][0] + b0, acc[ti][tj][1] + b1);
            *(uint32_t*)(out + (size_t)(r0 + 8) * 512 + col) = pack_bf16(acc[ti][tj][2] + b0, acc[ti][tj][3] + b1);
        }
    }
}

// ---------------------------------------------------------------------------
// Kernel 3: attention per (bc, kvh, t). 128 threads, softmax in registers.
// ---------------------------------------------------------------------------
#define QP 40   // Q/K row pitch (halves): 32 + 8
#define VP 72   // Vt row pitch (halves): 64 + 8

__global__ __launch_bounds__(128) void attn_tc()
{
    int bc = blockIdx.x, kvh = blockIdx.y, t = blockIdx.z;
    __shared__ __nv_bfloat16 Qs[2 * 64 * QP];
    __shared__ __nv_bfloat16 Ks[64 * QP];
    __shared__ __nv_bfloat16 Vt[32 * VP];

    int tid = threadIdx.x, wid = tid >> 5, lane = tid & 31;
    int gid = lane >> 2, tig = lane & 3;

    const __nv_bfloat16* qb = g_qkv + (size_t)t * TT * 512 + (size_t)bc * 64 * 512;
    const __nv_bfloat16* kb = g_qkv + (size_t)(1 - t) * TT * 512 + (size_t)bc * 64 * 512;

    // Q: 2 heads x 64 rows x 4 16B-units
    #pragma unroll
    for (int p = 0; p < 4; p++) {
        int i = tid + p * 128;
        int hh = i >> 8, rem = i & 255, r = rem >> 2, u = rem & 3;
        cp_async16(smaddr(Qs + (hh * 64 + r) * QP + u * 8),
                   qb + (size_t)r * 512 + (kvh * 2 + hh) * 32 + u * 8);
    }
    // K
    #pragma unroll
    for (int p = 0; p < 2; p++) {
        int i = tid + p * 128;
        int r = i >> 2, u = i & 3;
        cp_async16(smaddr(Ks + r * QP + u * 8),
                   kb + (size_t)r * 512 + 256 + kvh * 32 + u * 8);
    }
    cp_commit();
    // V transposed (scalar)
    #pragma unroll
    for (int p = 0; p < 16; p++) {
        int i = tid + p * 128;
        int j = i >> 5, d = i & 31;
        Vt[d * VP + j] = kb[(size_t)j * 512 + 384 + kvh * 32 + d];
    }
    cp_wait0();
    __syncthreads();

    int hh = wid >> 1, mh = wid & 1;

    // QK^T: warp tile 32 rows x 64 cols, K=32 (2 k16 steps)
    uint32_t qaddr[2], kaddr[4];
    #pragma unroll
    for (int ti = 0; ti < 2; ti++)
        qaddr[ti] = smaddr(Qs) +
            (((hh * 64 + mh * 32 + ti * 16 + (lane & 15)) * QP + ((lane >> 4) << 3)) << 1);
    #pragma unroll
    for (int tg = 0; tg < 4; tg++)
        kaddr[tg] = smaddr(Ks) +
            (((tg * 16 + ((lane >> 4) << 3) + (lane & 7)) * QP + (((lane >> 3) & 1) << 3)) << 1);

    float acc[2][8][4];
    #pragma unroll
    for (int ti = 0; ti < 2; ti++)
        #pragma unroll
        for (int tj = 0; tj < 8; tj++)
            #pragma unroll
            for (int q = 0; q < 4; q++) acc[ti][tj][q] = 0.f;

    #pragma unroll
    for (int ksi = 0; ksi < 2; ksi++) {
        uint32_t a[2][4], bfr[8][2];
        #pragma unroll
        for (int ti = 0; ti < 2; ti++)
            ldsm4(a[ti][0], a[ti][1], a[ti][2], a[ti][3], qaddr[ti] + (ksi << 5));
        #pragma unroll
        for (int tg = 0; tg < 4; tg++)
            ldsm4(bfr[2*tg][0], bfr[2*tg][1], bfr[2*tg+1][0], bfr[2*tg+1][1],
                  kaddr[tg] + (ksi << 5));
        #pragma unroll
        for (int ti = 0; ti < 2; ti++)
            #pragma unroll
            for (int tj = 0; tj < 8; tj++)
                mma_bf16(acc[ti][tj], a[ti], bfr[tj]);
    }

    // Softmax in registers. Row r stats live in the 4 lanes sharing gid.
    const float scale = 0.17677669529663687f;  // 1/sqrt(32)
    #pragma unroll
    for (int ti = 0; ti < 2; ti++) {
        float m0 = -3.0e38f, m1 = -3.0e38f;
        #pragma unroll
        for (int tj = 0; tj < 8; tj++) {
            #pragma unroll
            for (int q = 0; q < 4; q++) acc[ti][tj][q] *= scale;
            m0 = fmaxf(m0, fmaxf(acc[ti][tj][0], acc[ti][tj][1]));
            m1 = fmaxf(m1, fmaxf(acc[ti][tj][2], acc[ti][tj][3]));
        }
        m0 = fmaxf(m0, __shfl_xor_sync(0xffffffffu, m0, 1));
        m0 = fmaxf(m0, __shfl_xor_sync(0xffffffffu, m0, 2));
        m1 = fmaxf(m1, __shfl_xor_sync(0xffffffffu, m1, 1));
        m1 = fmaxf(m1, __shfl_xor_sync(0xffffffffu, m1, 2));
        float s0 = 0.f, s1 = 0.f;
        #pragma unroll
        for (int tj = 0; tj < 8; tj++) {
            acc[ti][tj][0] = __expf(acc[ti][tj][0] - m0);
            acc[ti][tj][1] = __expf(acc[ti][tj][1] - m0);
            acc[ti][tj][2] = __expf(acc[ti][tj][2] - m1);
            acc[ti][tj][3] = __expf(acc[ti][tj][3] - m1);
            s0 += acc[ti][tj][0] + acc[ti][tj][1];
            s1 += acc[ti][tj][2] + acc[ti][tj][3];
        }
        s0 += __shfl_xor_sync(0xffffffffu, s0, 1);
        s0 += __shfl_xor_sync(0xffffffffu, s0, 2);
        s1 += __shfl_xor_sync(0xffffffffu, s1, 1);
        s1 += __shfl_xor_sync(0xffffffffu, s1, 2);
        float r0 = 1.f / s0, r1 = 1.f / s1;
        #pragma unroll
        for (int tj = 0; tj < 8; tj++) {
            acc[ti][tj][0] *= r0; acc[ti][tj][1] *= r0;
            acc[ti][tj][2] *= r1; acc[ti][tj][3] *= r1;
        }
    }

    // PV: probs (regs, bf16-packed) x Vt. K=64 (4 k16 steps), N=32.
    uint32_t vaddr[2];
    #pragma unroll
    for (int tg = 0; tg < 2; tg++)
        vaddr[tg] = smaddr(Vt) +
            (((tg * 16 + ((lane >> 4) << 3) + (lane & 7)) * VP + (((lane >> 3) & 1) << 3)) << 1);

    float o[2][4][4];
    #pragma unroll
    for (int ti = 0; ti < 2; ti++)
        #pragma unroll
        for (int tj = 0; tj < 4; tj++)
            #pragma unroll
            for (int q = 0; q < 4; q++) o[ti][tj][q] = 0.f;

    #pragma unroll
    for (int ksi = 0; ksi < 4; ksi++) {
        uint32_t bv[4][2];
        ldsm4(bv[0][0], bv[0][1], bv[1][0], bv[1][1], vaddr[0] + (ksi << 5));
        ldsm4(bv[2][0], bv[2][1], bv[3][0], bv[3][1], vaddr[1] + (ksi << 5));
        #pragma unroll
        for (int ti = 0; ti < 2; ti++) {
            int tj = ksi * 2;
            uint32_t ap[4];
            ap[0] = pack_bf16(acc[ti][tj][0], acc[ti][tj][1]);
            ap[1] = pack_bf16(acc[ti][tj][2], acc[ti][tj][3]);
            ap[2] = pack_bf16(acc[ti][tj+1][0], acc[ti][tj+1][1]);
            ap[3] = pack_bf16(acc[ti][tj+1][2], acc[ti][tj+1][3]);
            #pragma unroll
            for (int tj2 = 0; tj2 < 4; tj2++)
                mma_bf16(o[ti][tj2], ap, bv[tj2]);
        }
    }

    // Write O (bf16)
    __nv_bfloat16* O = g_att + (size_t)t * TT * 256 + (size_t)bc * 64 * 256 + (kvh * 2 + hh) * 32;
    #pragma unroll
    for (int ti = 0; ti < 2; ti++) {
        int r0 = mh * 32 + ti * 16 + gid;
        #pragma unroll
        for (int tj2 = 0; tj2 < 4; tj2++) {
            int col = tj2 * 8 + 2 * tig;
            *(uint32_t*)(O + (size_t)r0 * 256 + col)       = pack_bf16(o[ti][tj2][0], o[ti][tj2][1]);
            *(uint32_t*)(O + (size_t)(r0 + 8) * 256 + col) = pack_bf16(o[ti][tj2][2], o[ti][tj2][3]);
        }
    }
}

// ---------------------------------------------------------------------------
// Kernel 4: output projection + bias + gate + residual. grid (512, 2), block 512.
// ---------------------------------------------------------------------------
__global__ __launch_bounds__(512) void out_tc(
    const float* __restrict__ x_spec, const float* __restrict__ x_spat,
    const float* __restrict__ bo_s2t, const float* __restrict__ bo_t2s,
    const float* __restrict__ gate_spec, const float* __restrict__ gate_spat,
    float* __restrict__ d_out)
{
    int bc0 = blockIdx.x, t = blockIdx.y;
    const float* bo = t ? bo_t2s : bo_s2t;
    const float* x  = t ? x_spat : x_spec;
    float gv = t ? gate_spat[0] : gate_spec[0];
    float gate = 1.f / (1.f + __expf(-gv));

    extern __shared__ __nv_bfloat16 smb[];
    __nv_bfloat16* As = smb;               // [128][AP]
    __nv_bfloat16* Ws = smb + 128 * AP;    // [2][256][WP]

    int tid = threadIdx.x, wid = tid >> 5, lane = tid & 31;
    int gid = lane >> 2, tig = lane & 3;

    // A tile (bf16) via cp.async: 128 rows x 32 16B-units
    const __nv_bfloat16* A = g_att + (size_t)t * TT * 256 + (size_t)bc0 * 128 * 256;
    #pragma unroll
    for (int it = 0; it < 8; it++) {
        int idx = tid + it * 512;
        int r = idx >> 5, u = idx & 31;
        cp_async16(smaddr(As + r * AP + u * 8), A + (size_t)r * 256 + u * 8);
    }
    cp_commit();

    const __nv_bfloat16* Wg = g_wo[t];
    #pragma unroll
    for (int it = 0; it < 4; it++) {
        int idx = tid + it * 512;
        int n = idx >> 3, u = idx & 7;
        cp_async16(smaddr(Ws + n * WP + u * 8), Wg + n * 256 + u * 8);
    }
    cp_commit();

    int warp_m = wid >> 2, warp_n = wid & 3;
    uint32_t a_addr[2], b_addr[4];
    #pragma unroll
    for (int ti = 0; ti < 2; ti++)
        a_addr[ti] = smaddr(As) +
            (((warp_m * 32 + ti * 16 + (lane & 15)) * AP + ((lane >> 4) << 3)) << 1);
    #pragma unroll
    for (int tg = 0; tg < 4; tg++)
        b_addr[tg] = smaddr(Ws) +
            (((warp_n * 64 + tg * 16 + ((lane >> 4) << 3) + (lane & 7)) * WP +
              (((lane >> 3) & 1) << 3)) << 1);

    float acc[2][8][4];
    #pragma unroll
    for (int ti = 0; ti < 2; ti++)
        #pragma unroll
        for (int tj = 0; tj < 8; tj++)
            #pragma unroll
            for (int q = 0; q < 4; q++) acc[ti][tj][q] = 0.f;

    #pragma unroll
    for (int c = 0; c < 4; c++) {
        if (c < 3) {
            int buf = (c + 1) & 1;
            #pragma unroll
            for (int it = 0; it < 4; it++) {
                int idx = tid + it * 512;
                int n = idx >> 3, u = idx & 7;
                cp_async16(smaddr(Ws + buf * 256 * WP + n * WP + u * 8),
                           Wg + n * 256 + (c + 1) * 64 + u * 8);
            }
            cp_commit();
            cp_wait1();
        } else {
            cp_wait0();
        }
        __syncthreads();

        uint32_t wboff = ((c & 1) * 256 * WP) << 1;
        #pragma unroll
        for (int ksi = 0; ksi < 4; ksi++) {
            int kg = c * 64 + ksi * 16;
            uint32_t a[2][4], bfr[8][2];
            #pragma unroll
            for (int ti = 0; ti < 2; ti++)
                ldsm4(a[ti][0], a[ti][1], a[ti][2], a[ti][3], a_addr[ti] + (kg << 1));
            #pragma unroll
            for (int tg = 0; tg < 4; tg++)
                ldsm4(bfr[2*tg][0], bfr[2*tg][1], bfr[2*tg+1][0], bfr[2*tg+1][1],
                      b_addr[tg] + wboff + (ksi << 5));
            #pragma unroll
            for (int ti = 0; ti < 2; ti++)
                #pragma unroll
                for (int tj = 0; tj < 8; tj++)
                    mma_bf16(acc[ti][tj], a[ti], bfr[tj]);
        }
        __syncthreads();
    }

    // Epilogue: bias + gate + residual, scatter back to (B,S,C,D)
    #pragma unroll
    for (int ti = 0; ti < 2; ti++) {
        #pragma unroll
        for (int half = 0; half < 2; half++) {
            int r = warp_m * 32 + ti * 16 + gid + half * 8;
            int bc = bc0 * 2 + (r >> 6);
            int s = r & 63, b = bc >> 7, c = bc & 127;
            size_t gb = (((size_t)b * 64 + s) * 128 + c) * 256;
            #pragma unroll
            for (int tj = 0; tj < 8; tj++) {
                int col = warp_n * 64 + tj * 8 + 2 * tig;
                float a0 = acc[ti][tj][half * 2 + 0] + bo[col];
                float a1 = acc[ti][tj][half * 2 + 1] + bo[col + 1];
                float2 xv = *(const float2*)(x + gb + col);
                float2 ov = make_float2(xv.x + gate * a0, xv.y + gate * a1);
                *(float2*)(d_out + (size_t)t * BSCD + gb + col) = ov;
            }
        }
    }
}

// ---------------------------------------------------------------------------
// Host launcher
// ---------------------------------------------------------------------------
extern "C" void kernel_launch(void* const* d_in, const int* in_sizes, int n_in,
                              void* d_out, int out_size)
{
    const float* x_spec      = (const float*)d_in[0];
    const float* x_spat      = (const float*)d_in[1];
    const float* ln_spec_q_g = (const float*)d_in[2];
    const float* ln_spec_q_b = (const float*)d_in[3];
    const float* ln_spec_kv_g= (const float*)d_in[4];
    const float* ln_spec_kv_b= (const float*)d_in[5];
    const float* ln_spat_q_g = (const float*)d_in[6];
    const float* ln_spat_q_b = (const float*)d_in[7];
    const float* ln_spat_kv_g= (const float*)d_in[8];
    const float* ln_spat_kv_b= (const float*)d_in[9];
    const float* Wq_s2t = (const float*)d_in[10];
    const float* bq_s2t = (const float*)d_in[11];
    const float* Wk_s2t = (const float*)d_in[12];
    const float* bk_s2t = (const float*)d_in[13];
    const float* Wv_s2t = (const float*)d_in[14];
    const float* bv_s2t = (const float*)d_in[15];
    const float* Wo_s2t = (const float*)d_in[16];
    const float* bo_s2t = (const float*)d_in[17];
    const float* Wq_t2s = (const float*)d_in[18];
    const float* bq_t2s = (const float*)d_in[19];
    const float* Wk_t2s = (const float*)d_in[20];
    const float* bk_t2s = (const float*)d_in[21];
    const float* Wv_t2s = (const float*)d_in[22];
    const float* bv_t2s = (const float*)d_in[23];
    const float* Wo_t2s = (const float*)d_in[24];
    const float* bo_t2s = (const float*)d_in[25];
    const float* gate_spec = (const float*)d_in[26];
    const float* gate_spat = (const float*)d_in[27];
    float* out = (float*)d_out;

    cudaFuncSetAttribute(ln_qkv_tc, cudaFuncAttributeMaxDynamicSharedMemorySize, GEMM_SMEM);
    cudaFuncSetAttribute(out_tc,    cudaFuncAttributeMaxDynamicSharedMemorySize, GEMM_SMEM);

    prep_kernel<<<dim3(768, 2), 256>>>(
        Wq_s2t, bq_s2t, Wk_s2t, bk_s2t, Wv_s2t, bv_s2t,
        Wq_t2s, bq_t2s, Wk_t2s, bk_t2s, Wv_t2s, bv_t2s,
        Wo_s2t, Wo_t2s,
        ln_spec_q_g, ln_spec_q_b, ln_spec_kv_g, ln_spec_kv_b,
        ln_spat_q_g, ln_spat_q_b, ln_spat_kv_g, ln_spat_kv_b);

    ln_qkv_tc<<<dim3(512, 2, 2), 512, GEMM_SMEM>>>(x_spec, x_spat);

    attn_tc<<<dim3(BC, KVH, 2), 128>>>();

    out_tc<<<dim3(512, 2), 512, GEMM_SMEM>>>(
        x_spec, x_spat, bo_s2t, bo_t2s, gate_spec, gate_spat, out);
}